// round 12
// baseline (speedup 1.0000x reference)
#include <cuda_runtime.h>

// ModulatedConv2dWithUpsample: B=8, Cin=512, Cout=256, H=W=64, ks=3, wdim=512
// out: [8,256,128,128] fp32
//
// Parity planes (P,Q in [0,64], zero-padded x'):
//   EE[P,Q] = w00*x[P,Q] + w02*x[P,Q-1] + w20*x[P-1,Q] + w22*x[P-1,Q-1]
//   EO[P,Q] = w01*x[P,Q] + w21*x[P-1,Q]
//   OE[P,Q] = w10*x[P,Q] + w12*x[P,Q-1]
//   OO[P,Q] = w11*x[P,Q]
// tap (a,b): cls = (a&1)*2 + (b&1); x row = pi + (a!=2), col = qi + (b!=2)
//
// Main conv covers P,Q in [0,64) exactly (8x16 tiles, no waste). Border kernel
// covers P=64 row (taps w20,w22 -> EE ; w21 -> EO), Q=64 col (w02,w22 -> EE ;
// w12 -> OE) and the corner. OE/OO at P=64 and EO/OO at Q=64 are identically 0
// and live in never-written (zero-initialized) g_planes cells.

#define BB   8
#define CIN  512
#define COUT 256

__device__ float g_s[BB * CIN];
__device__ float g_demod[BB * COUT];
__device__ float g_wT[9 * CIN * COUT];        // [k][ci][co], scale applied
__device__ float g_wsq[COUT * CIN];           // sum_k (scale*w)^2
// planes: [cls(4)][b][co][P+1 (66 rows)][Q+2 (68 cols)] ; borders stay zero
__device__ float g_planes[(size_t)4 * BB * COUT * 66 * 68];

// ---------------------------------------------------------------- f32x2 helpers

__device__ __forceinline__ unsigned long long pk(float x) {
    unsigned long long r;
    unsigned xi = __float_as_uint(x);
    asm("mov.b64 %0, {%1, %1};" : "=l"(r) : "r"(xi));
    return r;
}
__device__ __forceinline__ void unpk(unsigned long long v, float& lo, float& hi) {
    asm("mov.b64 {%0, %1}, %2;" : "=f"(lo), "=f"(hi) : "l"(v));
}
#define FMA2(A, W, X) asm("fma.rn.f32x2 %0, %1, %2, %0;" : "+l"(A) : "l"(W), "l"(X))

// ---------------------------------------------------------------- prep kernels

__global__ void k_style(const float* __restrict__ style,
                        const float* __restrict__ mw,
                        const float* __restrict__ mb) {
    int gt = blockIdx.x * blockDim.x + threadIdx.x;
    int wid = gt >> 5, lane = gt & 31;
    if (wid >= BB * CIN) return;
    int b = wid >> 9, ci = wid & (CIN - 1);
    const float* sp = style + b * 512;
    const float* wp = mw + ci * 512;
    float sum = 0.f;
    for (int t = lane; t < 512; t += 32) sum = fmaf(sp[t], wp[t], sum);
#pragma unroll
    for (int off = 16; off; off >>= 1) sum += __shfl_xor_sync(0xffffffffu, sum, off);
    if (lane == 0) g_s[wid] = sum * 0.04419417382415922f + mb[ci];  // 1/sqrt(512)
}

__global__ void k_wprep(const float* __restrict__ w) {
    int idx = blockIdx.x * blockDim.x + threadIdx.x;
    if (idx >= COUT * CIN) return;
    int co = idx >> 9, ci = idx & 511;
    const float sc = 0.014731391274719742f;  // 1/sqrt(512*9)
    float q = 0.f;
#pragma unroll
    for (int k = 0; k < 9; k++) {
        float wv = sc * w[idx * 9 + k];
        q = fmaf(wv, wv, q);
        g_wT[(k * CIN + ci) * COUT + co] = wv;
    }
    g_wsq[idx] = q;  // [co][ci]
}

__global__ void k_demod() {
    int gt = blockIdx.x * blockDim.x + threadIdx.x;
    int wid = gt >> 5, lane = gt & 31;
    if (wid >= BB * COUT) return;
    int b = wid >> 8, co = wid & 255;
    float sum = 0.f;
    for (int ci = lane; ci < CIN; ci += 32) {
        float sv = g_s[b * CIN + ci];
        sum = fmaf(sv * sv, g_wsq[co * CIN + ci], sum);
    }
#pragma unroll
    for (int off = 16; off; off >>= 1) sum += __shfl_xor_sync(0xffffffffu, sum, off);
    if (lane == 0) g_demod[wid] = rsqrtf(sum + 1e-8f);
}

// ---------------------------------------------------------------- main conv

#define CK 16

// grid: (32 = 8 P-tiles x 4 Q-tiles over [0,64)^2, 8 co-tiles, 8 b); block 256
// per CTA: 32 co x 8 P x 16 Q x 4 classes; per thread: 4 co (2x f32x2) x 2x2 x 4 cls
__global__ __launch_bounds__(256, 2) void k_upconv(const float* __restrict__ x) {
    __shared__ float s_all[CIN];
    __shared__ float xs[CK][9][18];              // rows P0-1..P0+7, cols Q0-1..Q0+15
    __shared__ __align__(16) float ws[9][CK][32];

    const int b = blockIdx.z;
    const int cobase = blockIdx.y * 32;
    const int pt = blockIdx.x >> 2, qt = blockIdx.x & 3;
    const int P0 = pt * 8, Q0 = qt * 16;
    const int tid = threadIdx.x;
    const int cog = tid >> 5;            // warp id -> co quad (uniform per warp)
    const int sp = tid & 31;
    const int pl = (sp >> 3) * 2;        // 0,2,4,6
    const int ql = (sp & 7) * 2;         // 0..14

    for (int i = tid; i < CIN; i += 256) s_all[i] = g_s[b * CIN + i];

    unsigned long long acc[4][2][2][2];  // [cls][pi][qi][co-pair] as f32x2
#pragma unroll
    for (int c = 0; c < 4; c++)
#pragma unroll
        for (int pi = 0; pi < 2; pi++)
#pragma unroll
            for (int qi = 0; qi < 2; qi++) {
                acc[c][pi][qi][0] = 0ull;
                acc[c][pi][qi][1] = 0ull;
            }

    for (int cb = 0; cb < CIN; cb += CK) {
        __syncthreads();
        for (int e = tid; e < CK * 9 * 17; e += 256) {
            int ci = e / 153;
            int rem = e - ci * 153;
            int r = rem / 17;
            int c = rem - r * 17;
            int gi = P0 - 1 + r, gj = Q0 - 1 + c;
            float v = 0.f;
            if ((unsigned)gi < 64u && (unsigned)gj < 64u)
                v = x[((b * CIN + cb + ci) * 64 + gi) * 64 + gj] * s_all[cb + ci];
            xs[ci][r][c] = v;
        }
        for (int e = tid; e < 9 * CK * 32; e += 256) {
            int k = e / (CK * 32);
            int rem = e - k * (CK * 32);
            int ci = rem >> 5;
            int co = rem & 31;
            ws[k][ci][co] = g_wT[(k * CIN + cb + ci) * COUT + cobase + co];
        }
        __syncthreads();

#pragma unroll 2
        for (int ci = 0; ci < CK; ci++) {
            unsigned long long xp[3][3];
#pragma unroll
            for (int rr = 0; rr < 3; rr++)
#pragma unroll
                for (int cc = 0; cc < 3; cc++)
                    xp[rr][cc] = pk(xs[ci][pl + rr][ql + cc]);
#pragma unroll
            for (int a = 0; a < 3; a++)
#pragma unroll
                for (int b2 = 0; b2 < 3; b2++) {
                    const int k = a * 3 + b2;
                    const int cls = (a & 1) * 2 + (b2 & 1);
                    ulonglong2 w2 = *reinterpret_cast<const ulonglong2*>(&ws[k][ci][cog * 4]);
#pragma unroll
                    for (int pi = 0; pi < 2; pi++)
#pragma unroll
                        for (int qi = 0; qi < 2; qi++) {
                            unsigned long long xv = xp[pi + (a != 2)][qi + (b2 != 2)];
                            FMA2(acc[cls][pi][qi][0], w2.x, xv);
                            FMA2(acc[cls][pi][qi][1], w2.y, xv);
                        }
                }
        }
    }

    float dm[4];
#pragma unroll
    for (int l = 0; l < 4; l++) dm[l] = g_demod[b * COUT + cobase + cog * 4 + l];

#pragma unroll
    for (int cls = 0; cls < 4; cls++)
#pragma unroll
        for (int pi = 0; pi < 2; pi++) {
            int P = P0 + pl + pi;           // < 64 always
            float v[2][4];                  // [qi][l]
#pragma unroll
            for (int qi = 0; qi < 2; qi++)
#pragma unroll
                for (int j = 0; j < 2; j++)
                    unpk(acc[cls][pi][qi][j], v[qi][2 * j], v[qi][2 * j + 1]);
            size_t base = ((((size_t)cls * BB + b) * COUT + cobase + cog * 4) * 66 + (P + 1)) * 68
                          + (Q0 + ql + 2);
#pragma unroll
            for (int l = 0; l < 4; l++)
                *reinterpret_cast<float2*>(&g_planes[base + (size_t)l * 66 * 68]) =
                    make_float2(v[0][l] * dm[l], v[1][l] * dm[l]);
        }
}

// ---------------------------------------------------------------- border kernel

// grid (16, 8): blockIdx.x = side*8 + cotile, blockIdx.y = b; block 256.
// side 0: P=64 row (positions Q=0..64, reads x'[63,*]);
// side 1: Q=64 col (positions P=0..63, reads x'[*,63]).
__global__ void k_border(const float* __restrict__ x) {
    __shared__ float s_all[CIN];
    __shared__ float xr[32][80];     // [ci][pos+1], pos in [-1..63]; [65..79] stay 0
    __shared__ float ws3[3][32][32]; // [tap][ci][co]

    const int side = blockIdx.x >> 3;
    const int cobase = (blockIdx.x & 7) * 32;
    const int b = blockIdx.y;
    const int tid = threadIdx.x;
    const int co = tid & 31;
    const int pg = tid >> 5;

    const int k0 = side ? 2 : 6;  // w02 / w20
    const int k1 = 8;             // w22
    const int k2 = side ? 5 : 7;  // w12 / w21
    const int cls2 = side ? 2 : 1;  // OE / EO
    const int maxpos = side ? 63 : 64;

    for (int i = tid; i < CIN; i += 256) s_all[i] = g_s[b * CIN + i];
    for (int e = tid; e < 32 * 80; e += 256) {
        int ci = e / 80, c = e - ci * 80;
        if (c == 0 || c >= 65) xr[ci][c] = 0.f;
    }

    float accA[9], accB[9];
#pragma unroll
    for (int i = 0; i < 9; i++) { accA[i] = 0.f; accB[i] = 0.f; }

    for (int cb = 0; cb < CIN; cb += 32) {
        __syncthreads();
        for (int e = tid; e < 32 * 64; e += 256) {
            int ci = e >> 6, q = e & 63;
            int gi = side ? q : 63;
            int gj = side ? 63 : q;
            xr[ci][q + 1] = x[((b * CIN + cb + ci) * 64 + gi) * 64 + gj] * s_all[cb + ci];
        }
        for (int e = tid; e < 3 * 32 * 32; e += 256) {
            int t = e >> 10;
            int rem = e & 1023;
            int ci = rem >> 5, c = rem & 31;
            int k = (t == 0) ? k0 : (t == 1) ? k1 : k2;
            ws3[t][ci][c] = g_wT[(k * CIN + cb + ci) * COUT + cobase + c];
        }
        __syncthreads();

        for (int ci = 0; ci < 32; ci++) {
            float wa = ws3[0][ci][co];
            float wb = ws3[1][ci][co];
            float wc = ws3[2][ci][co];
#pragma unroll
            for (int i = 0; i < 9; i++) {
                int pos = pg + 8 * i;       // may exceed maxpos; xr padding is 0
                float xA = xr[ci][pos + 1];
                float xB = xr[ci][pos];
                accA[i] = fmaf(wa, xA, fmaf(wb, xB, accA[i]));
                accB[i] = fmaf(wc, xA, accB[i]);
            }
        }
    }

    float dm = g_demod[b * COUT + cobase + co];
#pragma unroll
    for (int i = 0; i < 9; i++) {
        int pos = pg + 8 * i;
        if (pos > maxpos) continue;
        size_t cbase = (size_t)(b * COUT + cobase + co) * 66;
        size_t idx;
        if (side == 0)
            idx = (cbase + 65) * 68 + (pos + 2);         // P=64 row
        else
            idx = (cbase + pos + 1) * 68 + 66;            // Q=64 col
        const size_t clsStride = (size_t)BB * COUT * 66 * 68;
        g_planes[idx] = accA[i] * dm;                     // EE
        g_planes[(size_t)cls2 * clsStride + idx] = accB[i] * dm;
    }
}

// ---------------------------------------------------------------- blur epilogue

__global__ void k_blur(float* __restrict__ out) {
    __shared__ float R[2][68];  // R[q-parity][Qc+1], row-blurred
    const int u = blockIdx.x, co = blockIdx.y, b = blockIdx.z;
    const int tid = threadIdx.x;
    const int U = u >> 1, pu = u & 1;
    int rP[4], rcls[4];
    const float rw[4] = {0.25f, 0.75f, 0.75f, 0.25f};
    if (pu == 0) {
        rcls[0] = 2; rP[0] = U - 1;
        rcls[1] = 0; rP[1] = U;
        rcls[2] = 2; rP[2] = U;
        rcls[3] = 0; rP[3] = U + 1;
    } else {
        rcls[0] = 0; rP[0] = U;
        rcls[1] = 2; rP[1] = U;
        rcls[2] = 0; rP[2] = U + 1;
        rcls[3] = 2; rP[3] = U + 1;
    }
    for (int idx = tid; idx < 2 * 66; idx += 128) {
        int pq = idx / 66;
        int qi = idx - pq * 66;
        float a = 0.f;
#pragma unroll
        for (int r = 0; r < 4; r++) {
            size_t off = ((((size_t)(rcls[r] + pq) * BB + b) * COUT + co) * 66 + (rP[r] + 1)) * 68 + (qi + 1);
            a = fmaf(rw[r], g_planes[off], a);
        }
        R[pq][qi] = a;
    }
    __syncthreads();
    int v = tid;
    int V = v >> 1, pv = v & 1;
    float res;
    if (pv == 0)
        res = 0.25f * R[1][V] + 0.75f * R[0][V + 1] + 0.75f * R[1][V + 1] + 0.25f * R[0][V + 2];
    else
        res = 0.25f * R[0][V + 1] + 0.75f * R[1][V + 1] + 0.75f * R[0][V + 2] + 0.25f * R[1][V + 2];
    out[(((size_t)b * COUT + co) * 128 + u) * 128 + v] = res;
}

// ---------------------------------------------------------------- launch

extern "C" void kernel_launch(void* const* d_in, const int* in_sizes, int n_in,
                              void* d_out, int out_size) {
    (void)in_sizes; (void)n_in; (void)out_size;
    const float* input      = (const float*)d_in[0];  // [8,512,64,64]
    const float* style      = (const float*)d_in[1];  // [8,512]
    const float* weight     = (const float*)d_in[2];  // [1,256,512,3,3]
    const float* mod_weight = (const float*)d_in[3];  // [512,512]
    const float* mod_bias   = (const float*)d_in[4];  // [512]
    float* out = (float*)d_out;                       // [8,256,128,128]

    k_style<<<512, 256>>>(style, mod_weight, mod_bias);
    k_wprep<<<512, 256>>>(weight);
    k_demod<<<256, 256>>>();
    dim3 g1(32, 8, 8);
    k_upconv<<<g1, 256>>>(input);
    dim3 gb(16, 8);
    k_border<<<gb, 256>>>(input);
    dim3 g2(128, 256, 8);
    k_blur<<<g2, 128>>>(out);
}

// round 13
// speedup vs baseline: 1.6368x; 1.6368x over previous
#include <cuda_runtime.h>

// ModulatedConv2dWithUpsample: B=8, Cin=512, Cout=256, H=W=64, ks=3, wdim=512
// out: [8,256,128,128] fp32
//
// Parity planes (P,Q in [0,64], zero-padded x'):
//   EE[P,Q] = w00*x[P,Q] + w02*x[P,Q-1] + w20*x[P-1,Q] + w22*x[P-1,Q-1]
//   EO[P,Q] = w01*x[P,Q] + w21*x[P-1,Q]
//   OE[P,Q] = w10*x[P,Q] + w12*x[P,Q-1]
//   OO[P,Q] = w11*x[P,Q]
// Main conv covers P,Q in [0,64) exactly (8x16 tiles). Border kernel covers
// P=64 / Q=64; the remaining border classes are identically zero and live in
// never-written (zero-initialized) g_planes cells.

#define BB   8
#define CIN  512
#define COUT 256

__device__ float g_s[BB * CIN];
__device__ float g_demod[BB * COUT];
__device__ float g_wT[9 * CIN * COUT];        // [k][ci][co], scale applied
__device__ float g_wsq[COUT * CIN];           // sum_k (scale*w)^2
// planes: [cls(4)][b][co][P+1 (66 rows)][Q+2 (68 cols)] ; borders stay zero
__device__ float g_planes[(size_t)4 * BB * COUT * 66 * 68];

// ---------------------------------------------------------------- prep kernels

__global__ void k_style(const float* __restrict__ style,
                        const float* __restrict__ mw,
                        const float* __restrict__ mb) {
    int gt = blockIdx.x * blockDim.x + threadIdx.x;
    int wid = gt >> 5, lane = gt & 31;
    if (wid >= BB * CIN) return;
    int b = wid >> 9, ci = wid & (CIN - 1);
    const float* sp = style + b * 512;
    const float* wp = mw + ci * 512;
    float sum = 0.f;
    for (int t = lane; t < 512; t += 32) sum = fmaf(sp[t], wp[t], sum);
#pragma unroll
    for (int off = 16; off; off >>= 1) sum += __shfl_xor_sync(0xffffffffu, sum, off);
    if (lane == 0) g_s[wid] = sum * 0.04419417382415922f + mb[ci];  // 1/sqrt(512)
}

__global__ void k_wprep(const float* __restrict__ w) {
    int idx = blockIdx.x * blockDim.x + threadIdx.x;
    if (idx >= COUT * CIN) return;
    int co = idx >> 9, ci = idx & 511;
    const float sc = 0.014731391274719742f;  // 1/sqrt(512*9)
    float q = 0.f;
#pragma unroll
    for (int k = 0; k < 9; k++) {
        float wv = sc * w[idx * 9 + k];
        q = fmaf(wv, wv, q);
        g_wT[(k * CIN + ci) * COUT + co] = wv;
    }
    g_wsq[idx] = q;  // [co][ci]
}

__global__ void k_demod() {
    int gt = blockIdx.x * blockDim.x + threadIdx.x;
    int wid = gt >> 5, lane = gt & 31;
    if (wid >= BB * COUT) return;
    int b = wid >> 8, co = wid & 255;
    float sum = 0.f;
    for (int ci = lane; ci < CIN; ci += 32) {
        float sv = g_s[b * CIN + ci];
        sum = fmaf(sv * sv, g_wsq[co * CIN + ci], sum);
    }
#pragma unroll
    for (int off = 16; off; off >>= 1) sum += __shfl_xor_sync(0xffffffffu, sum, off);
    if (lane == 0) g_demod[wid] = rsqrtf(sum + 1e-8f);
}

// ---------------------------------------------------------------- main conv

#define CK 16
#define XS_STRIDE (CK * 9 * 32)   // 4608 floats per xs buffer (row stride 32)
#define WS_STRIDE (9 * CK * 32)   // 4608 floats per ws buffer
#define SMEM_FLOATS (512 + 2 * XS_STRIDE + 2 * WS_STRIDE)
#define SMEM_BYTES (SMEM_FLOATS * 4)

// per-row XOR swizzle: with row stride 32 floats, lanes (q 0..7 step 2, g 0..3)
// hit banks ((2q+cc) ^ S(2g+rr)); S gives the 4 pl-groups the 4 (bit0,bit4)
// cosets -> conflict-free for every tap.
__device__ __forceinline__ int swz(int r) {
    return ((r >> 1) & 1) | (((r >> 2) & 1) << 4);
}

#define FMA4(A, W, X)                      \
    do {                                   \
        (A).x = fmaf((W).x, (X), (A).x);   \
        (A).y = fmaf((W).y, (X), (A).y);   \
        (A).z = fmaf((W).z, (X), (A).z);   \
        (A).w = fmaf((W).w, (X), (A).w);   \
    } while (0)

// grid: (32 = 8 P-tiles x 4 Q-tiles over [0,64)^2, 8 co-tiles, 8 b); block 256
// per CTA: 32 co x 8 P x 16 Q x 4 classes; per thread: 4 co x 2x2 x 4 cls
__global__ __launch_bounds__(256, 2) void k_upconv(const float* __restrict__ x) {
    extern __shared__ float dsm[];
    float* s_all = dsm;                         // 512
    float* xsm   = dsm + 512;                   // 2 buffers
    float* wsm   = dsm + 512 + 2 * XS_STRIDE;   // 2 buffers

    const int b = blockIdx.z;
    const int cobase = blockIdx.y * 32;
    const int pt = blockIdx.x >> 2, qt = blockIdx.x & 3;
    const int P0 = pt * 8, Q0 = qt * 16;
    const int tid = threadIdx.x;
    const int cog = tid >> 5;            // warp id -> co quad (uniform per warp)
    const int sp = tid & 31;
    const int pl = (sp >> 3) * 2;        // 0,2,4,6
    const int ql = (sp & 7) * 2;         // 0..14

    for (int i = tid; i < CIN; i += 256) s_all[i] = g_s[b * CIN + i];

    // precomputed xs offsets (floats, within one ci slice of 288)
    int xoff[3][3];
#pragma unroll
    for (int rr = 0; rr < 3; rr++) {
        int r = pl + rr, s = swz(r);
#pragma unroll
        for (int cc = 0; cc < 3; cc++) xoff[rr][cc] = r * 32 + ((ql + cc) ^ s);
    }

    __syncthreads();  // s_all ready for prologue staging

    // prologue: stage xs for cb=0 directly (buffer 0)
    for (int e = tid; e < CK * 9 * 17; e += 256) {
        int ci = e / 153;
        int rem = e - ci * 153;
        int r = rem / 17;
        int c = rem - r * 17;
        int gi = P0 - 1 + r, gj = Q0 - 1 + c;
        float v = 0.f;
        if ((unsigned)gi < 64u && (unsigned)gj < 64u)
            v = x[((b * CIN + ci) * 64 + gi) * 64 + gj];
        xsm[ci * 288 + r * 32 + (c ^ swz(r))] = v * s_all[ci];
    }
    // prologue: cp.async ws for cb=0 into buffer 0
    for (int e = tid; e < 9 * CK * 8; e += 256) {
        int k = e >> 7;
        int rem = e & 127;
        int ci = rem >> 3;
        int q4 = (rem & 7) << 2;
        unsigned dst = (unsigned)__cvta_generic_to_shared(&wsm[(k * CK + ci) * 32 + q4]);
        const float* src = &g_wT[(size_t)(k * CIN + ci) * COUT + cobase + q4];
        asm volatile("cp.async.cg.shared.global [%0], [%1], 16;" :: "r"(dst), "l"(src));
    }
    asm volatile("cp.async.commit_group;" ::: "memory");

    float4 acc[4][2][2];
#pragma unroll
    for (int c = 0; c < 4; c++)
#pragma unroll
        for (int pi = 0; pi < 2; pi++)
#pragma unroll
            for (int qi = 0; qi < 2; qi++)
                acc[c][pi][qi] = make_float4(0.f, 0.f, 0.f, 0.f);

    for (int it = 0; it < CIN / CK; it++) {
        const int cb = it * CK;
        const int buf = it & 1;
        const bool more = (it < CIN / CK - 1);

        // prefetch next xs chunk into registers (LDGs in flight over compute)
        float xn[10];
        if (more) {
#pragma unroll
            for (int i = 0; i < 10; i++) {
                int e = tid + 256 * i;
                float v = 0.f;
                if (e < CK * 9 * 17) {
                    int ci = e / 153;
                    int rem = e - ci * 153;
                    int r = rem / 17;
                    int c = rem - r * 17;
                    int gi = P0 - 1 + r, gj = Q0 - 1 + c;
                    if ((unsigned)gi < 64u && (unsigned)gj < 64u)
                        v = x[((b * CIN + cb + CK + ci) * 64 + gi) * 64 + gj];
                }
                xn[i] = v;
            }
            // cp.async next ws into other buffer
            for (int e = tid; e < 9 * CK * 8; e += 256) {
                int k = e >> 7;
                int rem = e & 127;
                int ci = rem >> 3;
                int q4 = (rem & 7) << 2;
                unsigned dst = (unsigned)__cvta_generic_to_shared(
                    &wsm[(buf ^ 1) * WS_STRIDE + (k * CK + ci) * 32 + q4]);
                const float* src = &g_wT[(size_t)(k * CIN + cb + CK + ci) * COUT + cobase + q4];
                asm volatile("cp.async.cg.shared.global [%0], [%1], 16;" :: "r"(dst), "l"(src));
            }
        }
        asm volatile("cp.async.commit_group;" ::: "memory");
        asm volatile("cp.async.wait_group 1;" ::: "memory");  // current ws done
        __syncthreads();  // ws + xs[buf] visible to all

        const float* xbase = &xsm[buf * XS_STRIDE];
        const float* wbase = &wsm[buf * WS_STRIDE];

#pragma unroll 2
        for (int ci = 0; ci < CK; ci++) {
            float xv[3][3];
#pragma unroll
            for (int rr = 0; rr < 3; rr++)
#pragma unroll
                for (int cc = 0; cc < 3; cc++)
                    xv[rr][cc] = xbase[ci * 288 + xoff[rr][cc]];
            float4 wq[9];
#pragma unroll
            for (int k = 0; k < 9; k++)
                wq[k] = *reinterpret_cast<const float4*>(&wbase[(k * CK + ci) * 32 + cog * 4]);
#pragma unroll
            for (int pi = 0; pi < 2; pi++)
#pragma unroll
                for (int qi = 0; qi < 2; qi++) {
                    float xc = xv[pi + 1][qi + 1];  // x[P,Q]
                    float xl = xv[pi + 1][qi];      // x[P,Q-1]
                    float xu = xv[pi][qi + 1];      // x[P-1,Q]
                    float xd = xv[pi][qi];          // x[P-1,Q-1]
                    FMA4(acc[0][pi][qi], wq[0], xc);  // EE: w00
                    FMA4(acc[0][pi][qi], wq[2], xl);  //     w02
                    FMA4(acc[0][pi][qi], wq[6], xu);  //     w20
                    FMA4(acc[0][pi][qi], wq[8], xd);  //     w22
                    FMA4(acc[1][pi][qi], wq[1], xc);  // EO: w01
                    FMA4(acc[1][pi][qi], wq[7], xu);  //     w21
                    FMA4(acc[2][pi][qi], wq[3], xc);  // OE: w10
                    FMA4(acc[2][pi][qi], wq[5], xl);  //     w12
                    FMA4(acc[3][pi][qi], wq[4], xc);  // OO: w11
                }
        }

        // store prefetched xs into the other buffer (modulate here)
        if (more) {
#pragma unroll
            for (int i = 0; i < 10; i++) {
                int e = tid + 256 * i;
                if (e < CK * 9 * 17) {
                    int ci = e / 153;
                    int rem = e - ci * 153;
                    int r = rem / 17;
                    int c = rem - r * 17;
                    xsm[(buf ^ 1) * XS_STRIDE + ci * 288 + r * 32 + (c ^ swz(r))] =
                        xn[i] * s_all[cb + CK + ci];
                }
            }
        }
    }

    float dm[4];
#pragma unroll
    for (int l = 0; l < 4; l++) dm[l] = g_demod[b * COUT + cobase + cog * 4 + l];

#pragma unroll
    for (int cls = 0; cls < 4; cls++)
#pragma unroll
        for (int pi = 0; pi < 2; pi++) {
            int P = P0 + pl + pi;  // < 64 always
            const float* a0 = reinterpret_cast<const float*>(&acc[cls][pi][0]);
            const float* a1 = reinterpret_cast<const float*>(&acc[cls][pi][1]);
            size_t base = ((((size_t)cls * BB + b) * COUT + cobase + cog * 4) * 66 + (P + 1)) * 68
                          + (Q0 + ql + 2);
#pragma unroll
            for (int l = 0; l < 4; l++)
                *reinterpret_cast<float2*>(&g_planes[base + (size_t)l * 66 * 68]) =
                    make_float2(a0[l] * dm[l], a1[l] * dm[l]);
        }
}

// ---------------------------------------------------------------- border kernel

// grid (16, 8): blockIdx.x = side*8 + cotile, blockIdx.y = b; block 256.
// side 0: P=64 row (positions Q=0..64, reads x'[63,*]);
// side 1: Q=64 col (positions P=0..63, reads x'[*,63]).
__global__ void k_border(const float* __restrict__ x) {
    __shared__ float s_all[CIN];
    __shared__ float xr[32][80];     // [ci][pos+1], pos in [-1..63]; [65..79] stay 0
    __shared__ float ws3[3][32][32]; // [tap][ci][co]

    const int side = blockIdx.x >> 3;
    const int cobase = (blockIdx.x & 7) * 32;
    const int b = blockIdx.y;
    const int tid = threadIdx.x;
    const int co = tid & 31;
    const int pg = tid >> 5;

    const int k0 = side ? 2 : 6;  // w02 / w20
    const int k1 = 8;             // w22
    const int k2 = side ? 5 : 7;  // w12 / w21
    const int cls2 = side ? 2 : 1;  // OE / EO
    const int maxpos = side ? 63 : 64;

    for (int i = tid; i < CIN; i += 256) s_all[i] = g_s[b * CIN + i];
    for (int e = tid; e < 32 * 80; e += 256) {
        int ci = e / 80, c = e - ci * 80;
        if (c == 0 || c >= 65) xr[ci][c] = 0.f;
    }

    float accA[9], accB[9];
#pragma unroll
    for (int i = 0; i < 9; i++) { accA[i] = 0.f; accB[i] = 0.f; }

    for (int cb = 0; cb < CIN; cb += 32) {
        __syncthreads();
        for (int e = tid; e < 32 * 64; e += 256) {
            int ci = e >> 6, q = e & 63;
            int gi = side ? q : 63;
            int gj = side ? 63 : q;
            xr[ci][q + 1] = x[((b * CIN + cb + ci) * 64 + gi) * 64 + gj] * s_all[cb + ci];
        }
        for (int e = tid; e < 3 * 32 * 32; e += 256) {
            int t = e >> 10;
            int rem = e & 1023;
            int ci = rem >> 5, c = rem & 31;
            int k = (t == 0) ? k0 : (t == 1) ? k1 : k2;
            ws3[t][ci][c] = g_wT[(k * CIN + cb + ci) * COUT + cobase + c];
        }
        __syncthreads();

        for (int ci = 0; ci < 32; ci++) {
            float wa = ws3[0][ci][co];
            float wb = ws3[1][ci][co];
            float wc = ws3[2][ci][co];
#pragma unroll
            for (int i = 0; i < 9; i++) {
                int pos = pg + 8 * i;       // may exceed maxpos; xr padding is 0
                float xA = xr[ci][pos + 1];
                float xB = xr[ci][pos];
                accA[i] = fmaf(wa, xA, fmaf(wb, xB, accA[i]));
                accB[i] = fmaf(wc, xA, accB[i]);
            }
        }
    }

    float dm = g_demod[b * COUT + cobase + co];
#pragma unroll
    for (int i = 0; i < 9; i++) {
        int pos = pg + 8 * i;
        if (pos > maxpos) continue;
        size_t cbase = (size_t)(b * COUT + cobase + co) * 66;
        size_t idx;
        if (side == 0)
            idx = (cbase + 65) * 68 + (pos + 2);          // P=64 row
        else
            idx = (cbase + pos + 1) * 68 + 66;            // Q=64 col
        const size_t clsStride = (size_t)BB * COUT * 66 * 68;
        g_planes[idx] = accA[i] * dm;                     // EE
        g_planes[(size_t)cls2 * clsStride + idx] = accB[i] * dm;
    }
}

// ---------------------------------------------------------------- blur epilogue

__global__ void k_blur(float* __restrict__ out) {
    __shared__ float R[2][68];  // R[q-parity][Qc+1], row-blurred
    const int u = blockIdx.x, co = blockIdx.y, b = blockIdx.z;
    const int tid = threadIdx.x;
    const int U = u >> 1, pu = u & 1;
    int rP[4], rcls[4];
    const float rw[4] = {0.25f, 0.75f, 0.75f, 0.25f};
    if (pu == 0) {
        rcls[0] = 2; rP[0] = U - 1;
        rcls[1] = 0; rP[1] = U;
        rcls[2] = 2; rP[2] = U;
        rcls[3] = 0; rP[3] = U + 1;
    } else {
        rcls[0] = 0; rP[0] = U;
        rcls[1] = 2; rP[1] = U;
        rcls[2] = 0; rP[2] = U + 1;
        rcls[3] = 2; rP[3] = U + 1;
    }
    for (int idx = tid; idx < 2 * 66; idx += 128) {
        int pq = idx / 66;
        int qi = idx - pq * 66;
        float a = 0.f;
#pragma unroll
        for (int r = 0; r < 4; r++) {
            size_t off = ((((size_t)(rcls[r] + pq) * BB + b) * COUT + co) * 66 + (rP[r] + 1)) * 68 + (qi + 1);
            a = fmaf(rw[r], g_planes[off], a);
        }
        R[pq][qi] = a;
    }
    __syncthreads();
    int v = tid;
    int V = v >> 1, pv = v & 1;
    float res;
    if (pv == 0)
        res = 0.25f * R[1][V] + 0.75f * R[0][V + 1] + 0.75f * R[1][V + 1] + 0.25f * R[0][V + 2];
    else
        res = 0.25f * R[0][V + 1] + 0.75f * R[1][V + 1] + 0.75f * R[0][V + 2] + 0.25f * R[1][V + 2];
    out[(((size_t)b * COUT + co) * 128 + u) * 128 + v] = res;
}

// ---------------------------------------------------------------- launch

extern "C" void kernel_launch(void* const* d_in, const int* in_sizes, int n_in,
                              void* d_out, int out_size) {
    (void)in_sizes; (void)n_in; (void)out_size;
    const float* input      = (const float*)d_in[0];  // [8,512,64,64]
    const float* style      = (const float*)d_in[1];  // [8,512]
    const float* weight     = (const float*)d_in[2];  // [1,256,512,3,3]
    const float* mod_weight = (const float*)d_in[3];  // [512,512]
    const float* mod_bias   = (const float*)d_in[4];  // [512]
    float* out = (float*)d_out;                       // [8,256,128,128]

    cudaFuncSetAttribute(k_upconv, cudaFuncAttributeMaxDynamicSharedMemorySize, SMEM_BYTES);

    k_style<<<512, 256>>>(style, mod_weight, mod_bias);
    k_wprep<<<512, 256>>>(weight);
    k_demod<<<256, 256>>>();
    dim3 g1(32, 8, 8);
    k_upconv<<<g1, 256, SMEM_BYTES>>>(input);
    dim3 gb(16, 8);
    k_border<<<gb, 256>>>(input);
    dim3 g2(128, 256, 8);
    k_blur<<<g2, 128>>>(out);
}